// round 14
// baseline (speedup 1.0000x reference)
#include <cuda_runtime.h>
#include <cuda_bf16.h>
#include <cstdint>

#define DD 2048
#define BB 8192
#define BPAD 8704   /* 8192 + 4*128 worst-case segment padding */

// ---------------- device scratch (allocation-free rule) ----------------
__device__ __align__(16) __nv_bfloat16 g_a_hi[3][BPAD * DD]; // xs, h0, h1
__device__ __align__(16) __nv_bfloat16 g_a_lo[3][BPAD * DD];
__device__ __align__(16) __nv_bfloat16 g_w_hi[7 * DD * DD];  // W0 | W1(2) | W2(4), [n][k]
__device__ __align__(16) __nv_bfloat16 g_w_lo[7 * DD * DD];
__device__ int g_perm[BPAD];
__device__ int g_cnt[4], g_fill[4], g_segstart[5], g_ntiles;

// ---------------- PTX helpers ----------------
__device__ __forceinline__ uint32_t smem_u32(const void* p) {
    uint32_t a;
    asm("{ .reg .u64 t; cvta.to.shared.u64 t, %1; cvt.u32.u64 %0, t; }" : "=r"(a) : "l"(p));
    return a;
}

#define CP_ASYNC16(saddr, gptr) \
    asm volatile("cp.async.cg.shared.global [%0], [%1], 16;" :: "r"(saddr), "l"(gptr) : "memory")
#define CP_COMMIT() asm volatile("cp.async.commit_group;" ::: "memory")
#define CP_WAIT0()  asm volatile("cp.async.wait_group 0;" ::: "memory")
#define CP_WAIT1()  asm volatile("cp.async.wait_group 1;" ::: "memory")

#define LDSM_X4(r0, r1, r2, r3, addr) \
    asm volatile("ldmatrix.sync.aligned.m8n8.x4.shared.b16 {%0,%1,%2,%3}, [%4];" \
        : "=r"(r0), "=r"(r1), "=r"(r2), "=r"(r3) : "r"(addr))

#define MMA16816(d, a, b) \
    asm volatile("mma.sync.aligned.m16n8k16.row.col.f32.bf16.bf16.f32 " \
        "{%0,%1,%2,%3}, {%4,%5,%6,%7}, {%8,%9}, {%0,%1,%2,%3};" \
        : "+f"((d)[0]), "+f"((d)[1]), "+f"((d)[2]), "+f"((d)[3]) \
        : "r"((a)[0]), "r"((a)[1]), "r"((a)[2]), "r"((a)[3]), \
          "r"((b)[0]), "r"((b)[1]))

// SW128 swizzled SMEM address for element (row, kk) in a [128][64] bf16 tile
// (128B rows, 16B chunks; kk must be a multiple of 8)
__device__ __forceinline__ uint32_t sw_addr(uint32_t base, int row, int kk) {
    return base + row * 128 + ((((kk >> 3) ^ (row & 7))) << 4);
}

// ---------------- routing ----------------
__global__ void k_init() {
    int i = blockIdx.x * 256 + threadIdx.x;
    if (i < BPAD) g_perm[i] = -1;
    if (i < 4) { g_cnt[i] = 0; g_fill[i] = 0; }
}
__global__ void k_hist(const int* __restrict__ pm) {
    int i = blockIdx.x * 256 + threadIdx.x;
    if (i < BB) atomicAdd(&g_cnt[2 * pm[3 * i] + pm[3 * i + 1]], 1);
}
__global__ void k_scan() {
    int s = 0;
    for (int l = 0; l < 4; l++) { g_segstart[l] = s; s += (g_cnt[l] + 127) & ~127; }
    g_segstart[4] = s;
    g_ntiles = s / 128;
}
__global__ void k_scatter(const int* __restrict__ pm) {
    int i = blockIdx.x * 256 + threadIdx.x;
    if (i < BB) {
        int lf = 2 * pm[3 * i] + pm[3 * i + 1];
        int p = atomicAdd(&g_fill[lf], 1);
        g_perm[g_segstart[lf] + p] = i;
    }
}

// ---------------- gather + hi/lo split of x ----------------
__global__ void k_split_x(const float* __restrict__ x) {
    int r = blockIdx.x;
    int orig = g_perm[r];
    __nv_bfloat162* oh = (__nv_bfloat162*)(g_a_hi[0] + (size_t)r * DD);
    __nv_bfloat162* ol = (__nv_bfloat162*)(g_a_lo[0] + (size_t)r * DD);
    for (int j = threadIdx.x; j < DD / 2; j += blockDim.x) {
        float2 v = (orig >= 0) ? ((const float2*)x)[(size_t)orig * (DD / 2) + j]
                               : make_float2(0.f, 0.f);
        __nv_bfloat16 h0 = __float2bfloat16(v.x), h1 = __float2bfloat16(v.y);
        __nv_bfloat162 ph; ph.x = h0; ph.y = h1;
        oh[j] = ph;
        ol[j] = __floats2bfloat162_rn(v.x - __bfloat162float(h0), v.y - __bfloat162float(h1));
    }
}

// ---------------- transpose + hi/lo split of weights: out[n][k] = W[k][n] ----------------
__global__ void k_wsplit(const float* __restrict__ W, int base) {
    __shared__ float t[32][33];
    int e = blockIdx.z;
    const float* Ws = W + (size_t)e * DD * DD;
    __nv_bfloat16* Hh = g_w_hi + (size_t)(base + e) * DD * DD;
    __nv_bfloat16* Hl = g_w_lo + (size_t)(base + e) * DD * DD;
    int kb = blockIdx.y * 32, nb = blockIdx.x * 32;
    for (int r = threadIdx.y; r < 32; r += 8)
        t[r][threadIdx.x] = Ws[(size_t)(kb + r) * DD + nb + threadIdx.x];
    __syncthreads();
    for (int r = threadIdx.y; r < 32; r += 8) {
        float v = t[threadIdx.x][r];
        __nv_bfloat16 h = __float2bfloat16(v);
        size_t o = (size_t)(nb + r) * DD + kb + threadIdx.x;
        Hh[o] = h;
        Hl[o] = __float2bfloat16(v - __bfloat162float(h));
    }
}

// ---------------- fused bf16x3 GEMM + bias + relu (+ resplit / scatter) ----------------
// CTA tile 128x128, Kc=64, 8 warps (2x4), mma.sync m16n8k16, double-buffered cp.async.
#define STG 65536   /* per-stage SMEM: Ah 16K | Al 16K | Bh 16K | Bl 16K */

template <int L>
__global__ __launch_bounds__(256, 1) void k_gemm(const float* __restrict__ bias,
                                                 float* __restrict__ out) {
    const int mtile = blockIdx.x, ntile = blockIdx.y;
    if (mtile >= g_ntiles) return;

    int seg = 0;
    const int ts = mtile * 128;
    while (seg < 3 && ts >= g_segstart[seg + 1]) seg++;
    const int ex = (L == 0) ? 0 : (L == 1 ? (seg >> 1) : seg);
    const int wbase = ((L == 0) ? 0 : (L == 1 ? 1 : 3)) + ex;

    const __nv_bfloat16* Ah = g_a_hi[L] + (size_t)mtile * 128 * DD;
    const __nv_bfloat16* Al = g_a_lo[L] + (size_t)mtile * 128 * DD;
    const __nv_bfloat16* Bh = g_w_hi + (size_t)wbase * DD * DD + (size_t)ntile * 128 * DD;
    const __nv_bfloat16* Bl = g_w_lo + (size_t)wbase * DD * DD + (size_t)ntile * 128 * DD;
    const float* bv = bias + (size_t)ex * DD;

    extern __shared__ __align__(1024) char smem[];
    const uint32_t sb = smem_u32(smem);
    const int tid = threadIdx.x, wid = tid >> 5, lane = tid & 31;
    const int wm = wid >> 2, wn = wid & 3; // warp tile: rows wm*64, cols wn*32

    float acc[4][4][4];
#pragma unroll
    for (int mi = 0; mi < 4; mi++)
#pragma unroll
        for (int ni = 0; ni < 4; ni++)
#pragma unroll
            for (int r = 0; r < 4; r++) acc[mi][ni][r] = 0.f;

    // cp.async fill of one 64-wide K chunk into stage buffer
    auto prefetch = [&](int s, int buf) {
        const __nv_bfloat16* srcs[4] = {Ah, Al, Bh, Bl};
        const uint32_t stage = sb + buf * STG;
#pragma unroll
        for (int t = 0; t < 4; t++) {
            const __nv_bfloat16* src = srcs[t] + (size_t)s * 64;
            const uint32_t dst = stage + t * 16384;
#pragma unroll
            for (int i = tid; i < 1024; i += 256) {
                int row = i >> 3, u = i & 7;
                const __nv_bfloat16* g = src + (size_t)row * DD + u * 8;
                uint32_t a = dst + row * 128 + ((u ^ (row & 7)) << 4);
                CP_ASYNC16(a, g);
            }
        }
        CP_COMMIT();
    };

    // per-thread ldmatrix lane offsets
    const int rA = wm * 64 + (lane & 15);            // A row within tile
    const int kA = (lane >> 4) * 8;                  // A k offset within 16
    const int rB = wn * 32 + ((lane >> 4) << 3) + (lane & 7); // B row (n index)
    const int kB = ((lane >> 3) & 1) * 8;            // B k offset within 16

    prefetch(0, 0);

    for (int s = 0; s < 32; s++) {
        const int buf = s & 1;
        if (s + 1 < 32) { prefetch(s + 1, buf ^ 1); CP_WAIT1(); }
        else            { CP_WAIT0(); }
        __syncthreads();

        const uint32_t Ahi_b = sb + buf * STG;
        const uint32_t Alo_b = Ahi_b + 16384;
        const uint32_t Bhi_b = Ahi_b + 32768;
        const uint32_t Blo_b = Ahi_b + 49152;

#pragma unroll
        for (int ks = 0; ks < 4; ks++) {
            uint32_t ah[4][4], al[4][4], bh[4][2], bl[4][2];
            const int kk = ks * 16;
#pragma unroll
            for (int mi = 0; mi < 4; mi++) {
                LDSM_X4(ah[mi][0], ah[mi][1], ah[mi][2], ah[mi][3],
                        sw_addr(Ahi_b, rA + mi * 16, kk + kA));
                LDSM_X4(al[mi][0], al[mi][1], al[mi][2], al[mi][3],
                        sw_addr(Alo_b, rA + mi * 16, kk + kA));
            }
#pragma unroll
            for (int g = 0; g < 2; g++) {
                LDSM_X4(bh[g * 2][0], bh[g * 2][1], bh[g * 2 + 1][0], bh[g * 2 + 1][1],
                        sw_addr(Bhi_b, rB + g * 16, kk + kB));
                LDSM_X4(bl[g * 2][0], bl[g * 2][1], bl[g * 2 + 1][0], bl[g * 2 + 1][1],
                        sw_addr(Blo_b, rB + g * 16, kk + kB));
            }
#pragma unroll
            for (int mi = 0; mi < 4; mi++)
#pragma unroll
                for (int ni = 0; ni < 4; ni++) {
                    MMA16816(acc[mi][ni], ah[mi], bh[ni]);
                    MMA16816(acc[mi][ni], ah[mi], bl[ni]);
                    MMA16816(acc[mi][ni], al[mi], bh[ni]);
                }
        }
        __syncthreads();
    }

    // ---- epilogue: bias + relu, then hi/lo resplit (L<2) or perm-scatter (L==2) ----
    float bvals[4][2];
    const int ncol0 = ntile * 128 + wn * 32 + (lane & 3) * 2;
#pragma unroll
    for (int ni = 0; ni < 4; ni++) {
        bvals[ni][0] = bv[ncol0 + ni * 8];
        bvals[ni][1] = bv[ncol0 + ni * 8 + 1];
    }
#pragma unroll
    for (int mi = 0; mi < 4; mi++) {
        const int m0 = mtile * 128 + wm * 64 + mi * 16 + (lane >> 2);
#pragma unroll
        for (int ni = 0; ni < 4; ni++) {
            const int n0 = ncol0 + ni * 8;
#pragma unroll
            for (int h = 0; h < 2; h++) { // h=0: rows m0, h=1: rows m0+8
                const int grow = m0 + h * 8;
                float f0 = fmaxf(acc[mi][ni][h * 2 + 0] + bvals[ni][0], 0.f);
                float f1 = fmaxf(acc[mi][ni][h * 2 + 1] + bvals[ni][1], 0.f);
                if constexpr (L < 2) {
                    __nv_bfloat16 h0 = __float2bfloat16(f0), h1 = __float2bfloat16(f1);
                    __nv_bfloat162 ph; ph.x = h0; ph.y = h1;
                    __nv_bfloat162 pl = __floats2bfloat162_rn(
                        f0 - __bfloat162float(h0), f1 - __bfloat162float(h1));
                    size_t i2 = ((size_t)grow * DD + n0) >> 1;
                    ((__nv_bfloat162*)g_a_hi[L + 1])[i2] = ph;
                    ((__nv_bfloat162*)g_a_lo[L + 1])[i2] = pl;
                } else {
                    int orig = g_perm[grow];
                    if (orig >= 0) {
                        float2 v; v.x = f0; v.y = f1;
                        *(float2*)(out + (size_t)orig * DD + n0) = v;
                    }
                }
            }
        }
    }
}

// ---------------- launch ----------------
extern "C" void kernel_launch(void* const* d_in, const int* in_sizes, int n_in,
                              void* d_out, int out_size) {
    const float* x  = (const float*)d_in[0];
    const float* W0 = (const float*)d_in[1];
    const float* b0 = (const float*)d_in[2];
    const float* W1 = (const float*)d_in[3];
    const float* b1 = (const float*)d_in[4];
    const float* W2 = (const float*)d_in[5];
    const float* b2 = (const float*)d_in[6];
    const int* pm   = (const int*)d_in[7];
    float* out = (float*)d_out;

    const int smem = 2 * STG; // 128 KB
    cudaFuncSetAttribute(k_gemm<0>, cudaFuncAttributeMaxDynamicSharedMemorySize, smem);
    cudaFuncSetAttribute(k_gemm<1>, cudaFuncAttributeMaxDynamicSharedMemorySize, smem);
    cudaFuncSetAttribute(k_gemm<2>, cudaFuncAttributeMaxDynamicSharedMemorySize, smem);

    k_init<<<(BPAD + 255) / 256, 256>>>();
    k_hist<<<BB / 256, 256>>>(pm);
    k_scan<<<1, 1>>>();
    k_scatter<<<BB / 256, 256>>>(pm);
    k_split_x<<<BPAD, 256>>>(x);
    k_wsplit<<<dim3(64, 64, 1), dim3(32, 8)>>>(W0, 0);
    k_wsplit<<<dim3(64, 64, 2), dim3(32, 8)>>>(W1, 1);
    k_wsplit<<<dim3(64, 64, 4), dim3(32, 8)>>>(W2, 3);
    k_gemm<0><<<dim3(68, 16), 256, smem>>>(b0, nullptr);
    k_gemm<1><<<dim3(68, 16), 256, smem>>>(b1, nullptr);
    k_gemm<2><<<dim3(68, 16), 256, smem>>>(b2, out);
}

// round 15
// speedup vs baseline: 1.5692x; 1.5692x over previous
#include <cuda_runtime.h>
#include <cuda_bf16.h>
#include <cuda_fp16.h>
#include <cstdint>

#define DD 2048
#define BB 8192
#define BPAD 8704   /* 8192 + 4*128 worst-case segment padding */

// ---------------- device scratch (allocation-free rule) ----------------
__device__ __align__(16) __half g_a[3][BPAD * DD];      // x, h0, h1 (single fp16)
__device__ __align__(16) __half g_w_hi[7 * DD * DD];    // W0 | W1(2) | W2(4), [n][k]
__device__ __align__(16) __half g_w_lo[7 * DD * DD];
__device__ int g_perm[BPAD];
__device__ int g_cnt[4], g_fill[4], g_segstart[5], g_ntiles;

// ---------------- PTX helpers ----------------
__device__ __forceinline__ uint32_t smem_u32(const void* p) {
    uint32_t a;
    asm("{ .reg .u64 t; cvta.to.shared.u64 t, %1; cvt.u32.u64 %0, t; }" : "=r"(a) : "l"(p));
    return a;
}

#define CP_ASYNC16(saddr, gptr) \
    asm volatile("cp.async.cg.shared.global [%0], [%1], 16;" :: "r"(saddr), "l"(gptr) : "memory")
#define CP_COMMIT() asm volatile("cp.async.commit_group;" ::: "memory")
#define CP_WAIT0()  asm volatile("cp.async.wait_group 0;" ::: "memory")
#define CP_WAIT1()  asm volatile("cp.async.wait_group 1;" ::: "memory")

#define LDSM_X4(r0, r1, r2, r3, addr) \
    asm volatile("ldmatrix.sync.aligned.m8n8.x4.shared.b16 {%0,%1,%2,%3}, [%4];" \
        : "=r"(r0), "=r"(r1), "=r"(r2), "=r"(r3) : "r"(addr))

#define MMA16816(d, a, b) \
    asm volatile("mma.sync.aligned.m16n8k16.row.col.f32.f16.f16.f32 " \
        "{%0,%1,%2,%3}, {%4,%5,%6,%7}, {%8,%9}, {%0,%1,%2,%3};" \
        : "+f"((d)[0]), "+f"((d)[1]), "+f"((d)[2]), "+f"((d)[3]) \
        : "r"((a)[0]), "r"((a)[1]), "r"((a)[2]), "r"((a)[3]), \
          "r"((b)[0]), "r"((b)[1]))

// SW128 swizzled SMEM address for element (row, kk) in a [128][64] fp16 tile
__device__ __forceinline__ uint32_t sw_addr(uint32_t base, int row, int kk) {
    return base + row * 128 + ((((kk >> 3) ^ (row & 7))) << 4);
}

// ---------------- routing ----------------
__global__ void k_init() {
    int i = blockIdx.x * 256 + threadIdx.x;
    if (i < BPAD) g_perm[i] = -1;
    if (i < 4) { g_cnt[i] = 0; g_fill[i] = 0; }
}
__global__ void k_hist(const int* __restrict__ pm) {
    int i = blockIdx.x * 256 + threadIdx.x;
    if (i < BB) atomicAdd(&g_cnt[2 * pm[3 * i] + pm[3 * i + 1]], 1);
}
__global__ void k_scan() {
    int s = 0;
    for (int l = 0; l < 4; l++) { g_segstart[l] = s; s += (g_cnt[l] + 127) & ~127; }
    g_segstart[4] = s;
    g_ntiles = s / 128;
}
__global__ void k_scatter(const int* __restrict__ pm) {
    int i = blockIdx.x * 256 + threadIdx.x;
    if (i < BB) {
        int lf = 2 * pm[3 * i] + pm[3 * i + 1];
        int p = atomicAdd(&g_fill[lf], 1);
        g_perm[g_segstart[lf] + p] = i;
    }
}

// ---------------- gather x -> fp16 ----------------
__global__ void k_split_x(const float* __restrict__ x) {
    int r = blockIdx.x;
    int orig = g_perm[r];
    __half2* oh = (__half2*)(g_a[0] + (size_t)r * DD);
    for (int j = threadIdx.x; j < DD / 2; j += blockDim.x) {
        float2 v = (orig >= 0) ? ((const float2*)x)[(size_t)orig * (DD / 2) + j]
                               : make_float2(0.f, 0.f);
        oh[j] = __float22half2_rn(v);
    }
}

// ---------------- transpose + hi/lo fp16 split of weights: out[n][k] = W[k][n] ----------------
__global__ void k_wsplit(const float* __restrict__ W, int base) {
    __shared__ float t[32][33];
    int e = blockIdx.z;
    const float* Ws = W + (size_t)e * DD * DD;
    __half* Hh = g_w_hi + (size_t)(base + e) * DD * DD;
    __half* Hl = g_w_lo + (size_t)(base + e) * DD * DD;
    int kb = blockIdx.y * 32, nb = blockIdx.x * 32;
    for (int r = threadIdx.y; r < 32; r += 8)
        t[r][threadIdx.x] = Ws[(size_t)(kb + r) * DD + nb + threadIdx.x];
    __syncthreads();
    for (int r = threadIdx.y; r < 32; r += 8) {
        float v = t[threadIdx.x][r];
        __half h = __float2half_rn(v);
        size_t o = (size_t)(nb + r) * DD + kb + threadIdx.x;
        Hh[o] = h;
        Hl[o] = __float2half_rn(v - __half2float(h));
    }
}

// ---------------- fused fp16x2 GEMM + bias + relu (+ fp16 store / scatter) ----------------
// CTA tile 128x128, Kc=64, 8 warps (2x4), mma.sync m16n8k16, double-buffered cp.async,
// 2 CTAs/SM for cross-CTA load/compute overlap.
#define STG 49152   /* per-stage SMEM: A 16K | Bh 16K | Bl 16K */

template <int L>
__global__ __launch_bounds__(256, 2) void k_gemm(const float* __restrict__ bias,
                                                 float* __restrict__ out) {
    const int mtile = blockIdx.x, ntile = blockIdx.y;
    if (mtile >= g_ntiles) return;

    int seg = 0;
    const int ts = mtile * 128;
    while (seg < 3 && ts >= g_segstart[seg + 1]) seg++;
    const int ex = (L == 0) ? 0 : (L == 1 ? (seg >> 1) : seg);
    const int wbase = ((L == 0) ? 0 : (L == 1 ? 1 : 3)) + ex;

    const __half* A  = g_a[L] + (size_t)mtile * 128 * DD;
    const __half* Bh = g_w_hi + (size_t)wbase * DD * DD + (size_t)ntile * 128 * DD;
    const __half* Bl = g_w_lo + (size_t)wbase * DD * DD + (size_t)ntile * 128 * DD;
    const float* bv = bias + (size_t)ex * DD;

    extern __shared__ __align__(1024) char smem[];
    const uint32_t sb = smem_u32(smem);
    const int tid = threadIdx.x, wid = tid >> 5, lane = tid & 31;
    const int wm = wid >> 2, wn = wid & 3; // warp tile: rows wm*64, cols wn*32

    float acc[4][4][4];
#pragma unroll
    for (int mi = 0; mi < 4; mi++)
#pragma unroll
        for (int ni = 0; ni < 4; ni++)
#pragma unroll
            for (int r = 0; r < 4; r++) acc[mi][ni][r] = 0.f;

    // cp.async fill of one 64-wide K chunk (A, Bh, Bl) into stage buffer
    auto prefetch = [&](int s, int buf) {
        const __half* srcs[3] = {A, Bh, Bl};
        const uint32_t stage = sb + buf * STG;
#pragma unroll
        for (int t = 0; t < 3; t++) {
            const __half* src = srcs[t] + (size_t)s * 64;
            const uint32_t dst = stage + t * 16384;
#pragma unroll
            for (int i = tid; i < 1024; i += 256) {
                int row = i >> 3, u = i & 7;
                const __half* g = src + (size_t)row * DD + u * 8;
                uint32_t a = dst + row * 128 + ((u ^ (row & 7)) << 4);
                CP_ASYNC16(a, g);
            }
        }
        CP_COMMIT();
    };

    // per-thread ldmatrix lane offsets
    const int rA = wm * 64 + (lane & 15);                     // A row within tile
    const int kA = (lane >> 4) * 8;                           // A k offset within 16
    const int rB = wn * 32 + ((lane >> 4) << 3) + (lane & 7); // B row (n index)
    const int kB = ((lane >> 3) & 1) * 8;                     // B k offset within 16

    prefetch(0, 0);

    for (int s = 0; s < 32; s++) {
        const int buf = s & 1;
        if (s + 1 < 32) { prefetch(s + 1, buf ^ 1); CP_WAIT1(); }
        else            { CP_WAIT0(); }
        __syncthreads();

        const uint32_t A_b  = sb + buf * STG;
        const uint32_t Bh_b = A_b + 16384;
        const uint32_t Bl_b = A_b + 32768;

#pragma unroll
        for (int ks = 0; ks < 4; ks++) {
            uint32_t af[4][4], bh[4][2], bl[4][2];
            const int kk = ks * 16;
#pragma unroll
            for (int mi = 0; mi < 4; mi++)
                LDSM_X4(af[mi][0], af[mi][1], af[mi][2], af[mi][3],
                        sw_addr(A_b, rA + mi * 16, kk + kA));
#pragma unroll
            for (int g = 0; g < 2; g++) {
                LDSM_X4(bh[g * 2][0], bh[g * 2][1], bh[g * 2 + 1][0], bh[g * 2 + 1][1],
                        sw_addr(Bh_b, rB + g * 16, kk + kB));
                LDSM_X4(bl[g * 2][0], bl[g * 2][1], bl[g * 2 + 1][0], bl[g * 2 + 1][1],
                        sw_addr(Bl_b, rB + g * 16, kk + kB));
            }
#pragma unroll
            for (int mi = 0; mi < 4; mi++)
#pragma unroll
                for (int ni = 0; ni < 4; ni++) {
                    MMA16816(acc[mi][ni], af[mi], bh[ni]);
                    MMA16816(acc[mi][ni], af[mi], bl[ni]);
                }
        }
        __syncthreads();
    }

    // ---- epilogue: bias + relu, then fp16 store (L<2) or perm-scatter fp32 (L==2) ----
    float bvals[4][2];
    const int ncol0 = ntile * 128 + wn * 32 + (lane & 3) * 2;
#pragma unroll
    for (int ni = 0; ni < 4; ni++) {
        bvals[ni][0] = bv[ncol0 + ni * 8];
        bvals[ni][1] = bv[ncol0 + ni * 8 + 1];
    }
#pragma unroll
    for (int mi = 0; mi < 4; mi++) {
        const int m0 = mtile * 128 + wm * 64 + mi * 16 + (lane >> 2);
#pragma unroll
        for (int ni = 0; ni < 4; ni++) {
            const int n0 = ncol0 + ni * 8;
#pragma unroll
            for (int h = 0; h < 2; h++) { // h=0: rows m0, h=1: rows m0+8
                const int grow = m0 + h * 8;
                float f0 = fmaxf(acc[mi][ni][h * 2 + 0] + bvals[ni][0], 0.f);
                float f1 = fmaxf(acc[mi][ni][h * 2 + 1] + bvals[ni][1], 0.f);
                if constexpr (L < 2) {
                    float2 v; v.x = f0; v.y = f1;
                    ((__half2*)g_a[L + 1])[((size_t)grow * DD + n0) >> 1] =
                        __float22half2_rn(v);
                } else {
                    int orig = g_perm[grow];
                    if (orig >= 0) {
                        float2 v; v.x = f0; v.y = f1;
                        *(float2*)(out + (size_t)orig * DD + n0) = v;
                    }
                }
            }
        }
    }
}

// ---------------- launch ----------------
extern "C" void kernel_launch(void* const* d_in, const int* in_sizes, int n_in,
                              void* d_out, int out_size) {
    const float* x  = (const float*)d_in[0];
    const float* W0 = (const float*)d_in[1];
    const float* b0 = (const float*)d_in[2];
    const float* W1 = (const float*)d_in[3];
    const float* b1 = (const float*)d_in[4];
    const float* W2 = (const float*)d_in[5];
    const float* b2 = (const float*)d_in[6];
    const int* pm   = (const int*)d_in[7];
    float* out = (float*)d_out;

    const int smem = 2 * STG; // 96 KB
    cudaFuncSetAttribute(k_gemm<0>, cudaFuncAttributeMaxDynamicSharedMemorySize, smem);
    cudaFuncSetAttribute(k_gemm<1>, cudaFuncAttributeMaxDynamicSharedMemorySize, smem);
    cudaFuncSetAttribute(k_gemm<2>, cudaFuncAttributeMaxDynamicSharedMemorySize, smem);

    k_init<<<(BPAD + 255) / 256, 256>>>();
    k_hist<<<BB / 256, 256>>>(pm);
    k_scan<<<1, 1>>>();
    k_scatter<<<BB / 256, 256>>>(pm);
    k_split_x<<<BPAD, 256>>>(x);
    k_wsplit<<<dim3(64, 64, 1), dim3(32, 8)>>>(W0, 0);
    k_wsplit<<<dim3(64, 64, 2), dim3(32, 8)>>>(W1, 1);
    k_wsplit<<<dim3(64, 64, 4), dim3(32, 8)>>>(W2, 3);
    k_gemm<0><<<dim3(68, 16), 256, smem>>>(b0, nullptr);
    k_gemm<1><<<dim3(68, 16), 256, smem>>>(b1, nullptr);
    k_gemm<2><<<dim3(68, 16), 256, smem>>>(b2, out);
}

// round 16
// speedup vs baseline: 2.4736x; 1.5763x over previous
#include <cuda_runtime.h>
#include <cuda_bf16.h>
#include <cuda_fp16.h>
#include <cstdint>

#define DD 2048
#define BB 8192
#define BPAD 8704   /* 8192 + 4*128 worst-case segment padding */

// ---------------- device scratch (allocation-free rule) ----------------
__device__ __align__(16) __half g_a[3][BPAD * DD];   // x, h0, h1 (fp16)
__device__ __align__(16) __half g_w[7 * DD * DD];    // W0 | W1(2) | W2(4), [n][k] fp16
__device__ int g_perm[BPAD];
__device__ int g_cnt[4], g_fill[4], g_segstart[5], g_ntiles;

// ---------------- PTX helpers ----------------
__device__ __forceinline__ uint32_t smem_u32(const void* p) {
    uint32_t a;
    asm("{ .reg .u64 t; cvta.to.shared.u64 t, %1; cvt.u32.u64 %0, t; }" : "=r"(a) : "l"(p));
    return a;
}

#define CP_ASYNC16(saddr, gptr) \
    asm volatile("cp.async.cg.shared.global [%0], [%1], 16;" :: "r"(saddr), "l"(gptr) : "memory")
#define CP_COMMIT() asm volatile("cp.async.commit_group;" ::: "memory")
#define CP_WAIT2()  asm volatile("cp.async.wait_group 2;" ::: "memory")

#define LDSM_X4(r0, r1, r2, r3, addr) \
    asm volatile("ldmatrix.sync.aligned.m8n8.x4.shared.b16 {%0,%1,%2,%3}, [%4];" \
        : "=r"(r0), "=r"(r1), "=r"(r2), "=r"(r3) : "r"(addr))

#define MMA16816(d, a, b) \
    asm volatile("mma.sync.aligned.m16n8k16.row.col.f32.f16.f16.f32 " \
        "{%0,%1,%2,%3}, {%4,%5,%6,%7}, {%8,%9}, {%0,%1,%2,%3};" \
        : "+f"((d)[0]), "+f"((d)[1]), "+f"((d)[2]), "+f"((d)[3]) \
        : "r"((a)[0]), "r"((a)[1]), "r"((a)[2]), "r"((a)[3]), \
          "r"((b)[0]), "r"((b)[1]))

// SW128 swizzled SMEM address for element (row, kk) in a [128][64] fp16 tile
__device__ __forceinline__ uint32_t sw_addr(uint32_t base, int row, int kk) {
    return base + row * 128 + ((((kk >> 3) ^ (row & 7))) << 4);
}

// ---------------- routing ----------------
__global__ void k_init() {
    int i = blockIdx.x * 256 + threadIdx.x;
    if (i < BPAD) g_perm[i] = -1;
    if (i < 4) { g_cnt[i] = 0; g_fill[i] = 0; }
}
__global__ void k_hist(const int* __restrict__ pm) {
    int i = blockIdx.x * 256 + threadIdx.x;
    if (i < BB) atomicAdd(&g_cnt[2 * pm[3 * i] + pm[3 * i + 1]], 1);
}
__global__ void k_scan() {
    int s = 0;
    for (int l = 0; l < 4; l++) { g_segstart[l] = s; s += (g_cnt[l] + 127) & ~127; }
    g_segstart[4] = s;
    g_ntiles = s / 128;
}
__global__ void k_scatter(const int* __restrict__ pm) {
    int i = blockIdx.x * 256 + threadIdx.x;
    if (i < BB) {
        int lf = 2 * pm[3 * i] + pm[3 * i + 1];
        int p = atomicAdd(&g_fill[lf], 1);
        g_perm[g_segstart[lf] + p] = i;
    }
}

// ---------------- gather x -> fp16 ----------------
__global__ void k_split_x(const float* __restrict__ x) {
    int r = blockIdx.x;
    int orig = g_perm[r];
    __half2* oh = (__half2*)(g_a[0] + (size_t)r * DD);
    for (int j = threadIdx.x; j < DD / 2; j += blockDim.x) {
        float2 v = (orig >= 0) ? ((const float2*)x)[(size_t)orig * (DD / 2) + j]
                               : make_float2(0.f, 0.f);
        oh[j] = __float22half2_rn(v);
    }
}

// ---------------- transpose + fp16 convert of weights: out[n][k] = W[k][n] ----------------
__global__ void k_wsplit(const float* __restrict__ W, int base) {
    __shared__ float t[32][33];
    int e = blockIdx.z;
    const float* Ws = W + (size_t)e * DD * DD;
    __half* Hh = g_w + (size_t)(base + e) * DD * DD;
    int kb = blockIdx.y * 32, nb = blockIdx.x * 32;
    for (int r = threadIdx.y; r < 32; r += 8)
        t[r][threadIdx.x] = Ws[(size_t)(kb + r) * DD + nb + threadIdx.x];
    __syncthreads();
    for (int r = threadIdx.y; r < 32; r += 8)
        Hh[(size_t)(nb + r) * DD + kb + threadIdx.x] = __float2half_rn(t[threadIdx.x][r]);
}

// ---------------- fused fp16 GEMM + bias + relu (+ fp16 store / scatter) ----------------
// CTA tile 128x128, Kc=64, 8 warps (2x4), mma.sync m16n8k16,
// 3-stage cp.async pipeline, 2 CTAs/SM.
#define STG 32768   /* per-stage SMEM: A 16K | B 16K */

template <int L>
__global__ __launch_bounds__(256, 2) void k_gemm(const float* __restrict__ bias,
                                                 float* __restrict__ out) {
    const int mtile = blockIdx.x, ntile = blockIdx.y;
    if (mtile >= g_ntiles) return;

    int seg = 0;
    const int ts = mtile * 128;
    while (seg < 3 && ts >= g_segstart[seg + 1]) seg++;
    const int ex = (L == 0) ? 0 : (L == 1 ? (seg >> 1) : seg);
    const int wbase = ((L == 0) ? 0 : (L == 1 ? 1 : 3)) + ex;

    const __half* A = g_a[L] + (size_t)mtile * 128 * DD;
    const __half* B = g_w + (size_t)wbase * DD * DD + (size_t)ntile * 128 * DD;
    const float* bv = bias + (size_t)ex * DD;

    extern __shared__ __align__(1024) char smem[];
    const uint32_t sb = smem_u32(smem);
    const int tid = threadIdx.x, wid = tid >> 5, lane = tid & 31;
    const int wm = wid >> 2, wn = wid & 3; // warp tile: rows wm*64, cols wn*32

    float acc[4][4][4];
#pragma unroll
    for (int mi = 0; mi < 4; mi++)
#pragma unroll
        for (int ni = 0; ni < 4; ni++)
#pragma unroll
            for (int r = 0; r < 4; r++) acc[mi][ni][r] = 0.f;

    // cp.async fill of one 64-wide K chunk (A, B) into stage buffer s%3.
    // Always commits exactly one group (possibly empty) for uniform wait counts.
    auto prefetch = [&](int s) {
        if (s < 32) {
            const __half* srcs[2] = {A, B};
            const uint32_t stage = sb + (s % 3) * STG;
#pragma unroll
            for (int t = 0; t < 2; t++) {
                const __half* src = srcs[t] + (size_t)s * 64;
                const uint32_t dst = stage + t * 16384;
#pragma unroll
                for (int i = tid; i < 1024; i += 256) {
                    int row = i >> 3, u = i & 7;
                    const __half* g = src + (size_t)row * DD + u * 8;
                    uint32_t a = dst + row * 128 + ((u ^ (row & 7)) << 4);
                    CP_ASYNC16(a, g);
                }
            }
        }
        CP_COMMIT();
    };

    // per-thread ldmatrix lane offsets
    const int rA = wm * 64 + (lane & 15);                     // A row within tile
    const int kA = (lane >> 4) * 8;                           // A k offset within 16
    const int rB = wn * 32 + ((lane >> 4) << 3) + (lane & 7); // B row (n index)
    const int kB = ((lane >> 3) & 1) * 8;                     // B k offset within 16

    prefetch(0);
    prefetch(1);

    for (int s = 0; s < 32; s++) {
        prefetch(s + 2);
        CP_WAIT2();          // stage s complete; s+1, s+2 may be in flight
        __syncthreads();

        const uint32_t A_b = sb + (s % 3) * STG;
        const uint32_t B_b = A_b + 16384;

#pragma unroll
        for (int ks = 0; ks < 4; ks++) {
            uint32_t af[4][4], bf[4][2];
            const int kk = ks * 16;
#pragma unroll
            for (int mi = 0; mi < 4; mi++)
                LDSM_X4(af[mi][0], af[mi][1], af[mi][2], af[mi][3],
                        sw_addr(A_b, rA + mi * 16, kk + kA));
#pragma unroll
            for (int g = 0; g < 2; g++)
                LDSM_X4(bf[g * 2][0], bf[g * 2][1], bf[g * 2 + 1][0], bf[g * 2 + 1][1],
                        sw_addr(B_b, rB + g * 16, kk + kB));
#pragma unroll
            for (int mi = 0; mi < 4; mi++)
#pragma unroll
                for (int ni = 0; ni < 4; ni++)
                    MMA16816(acc[mi][ni], af[mi], bf[ni]);
        }
        __syncthreads();     // all reads of stage s done before it is refilled
    }

    // ---- epilogue: bias + relu, then fp16 store (L<2) or perm-scatter fp32 (L==2) ----
    float bvals[4][2];
    const int ncol0 = ntile * 128 + wn * 32 + (lane & 3) * 2;
#pragma unroll
    for (int ni = 0; ni < 4; ni++) {
        bvals[ni][0] = bv[ncol0 + ni * 8];
        bvals[ni][1] = bv[ncol0 + ni * 8 + 1];
    }
#pragma unroll
    for (int mi = 0; mi < 4; mi++) {
        const int m0 = mtile * 128 + wm * 64 + mi * 16 + (lane >> 2);
#pragma unroll
        for (int ni = 0; ni < 4; ni++) {
            const int n0 = ncol0 + ni * 8;
#pragma unroll
            for (int h = 0; h < 2; h++) { // h=0: rows m0, h=1: rows m0+8
                const int grow = m0 + h * 8;
                float f0 = fmaxf(acc[mi][ni][h * 2 + 0] + bvals[ni][0], 0.f);
                float f1 = fmaxf(acc[mi][ni][h * 2 + 1] + bvals[ni][1], 0.f);
                if constexpr (L < 2) {
                    float2 v; v.x = f0; v.y = f1;
                    ((__half2*)g_a[L + 1])[((size_t)grow * DD + n0) >> 1] =
                        __float22half2_rn(v);
                } else {
                    int orig = g_perm[grow];
                    if (orig >= 0) {
                        float2 v; v.x = f0; v.y = f1;
                        *(float2*)(out + (size_t)orig * DD + n0) = v;
                    }
                }
            }
        }
    }
}

// ---------------- launch ----------------
extern "C" void kernel_launch(void* const* d_in, const int* in_sizes, int n_in,
                              void* d_out, int out_size) {
    const float* x  = (const float*)d_in[0];
    const float* W0 = (const float*)d_in[1];
    const float* b0 = (const float*)d_in[2];
    const float* W1 = (const float*)d_in[3];
    const float* b1 = (const float*)d_in[4];
    const float* W2 = (const float*)d_in[5];
    const float* b2 = (const float*)d_in[6];
    const int* pm   = (const int*)d_in[7];
    float* out = (float*)d_out;

    const int smem = 3 * STG; // 96 KB per CTA, 2 CTAs/SM = 192 KB
    cudaFuncSetAttribute(k_gemm<0>, cudaFuncAttributeMaxDynamicSharedMemorySize, smem);
    cudaFuncSetAttribute(k_gemm<1>, cudaFuncAttributeMaxDynamicSharedMemorySize, smem);
    cudaFuncSetAttribute(k_gemm<2>, cudaFuncAttributeMaxDynamicSharedMemorySize, smem);

    k_init<<<(BPAD + 255) / 256, 256>>>();
    k_hist<<<BB / 256, 256>>>(pm);
    k_scan<<<1, 1>>>();
    k_scatter<<<BB / 256, 256>>>(pm);
    k_split_x<<<BPAD, 256>>>(x);
    k_wsplit<<<dim3(64, 64, 1), dim3(32, 8)>>>(W0, 0);
    k_wsplit<<<dim3(64, 64, 2), dim3(32, 8)>>>(W1, 1);
    k_wsplit<<<dim3(64, 64, 4), dim3(32, 8)>>>(W2, 3);
    k_gemm<0><<<dim3(68, 16), 256, smem>>>(b0, nullptr);
    k_gemm<1><<<dim3(68, 16), 256, smem>>>(b1, nullptr);
    k_gemm<2><<<dim3(68, 16), 256, smem>>>(b2, out);
}